// round 8
// baseline (speedup 1.0000x reference)
#include <cuda_runtime.h>
#include <cstdint>

#define Bn 16
#define Tn 12
#define BT 192          // B*T
#define Nn 325
#define Dd 64
#define Hh 4
#define Ee 2600
#define ET (Ee + Nn)    // 2925 edges incl. self loops
#define NBT (Nn * BT)   // 62400 (n,bt) pairs

typedef unsigned long long ull;

// ---------------- packed f32x2 helpers (sm_103a FFMA2) ----------------
__device__ __forceinline__ void ffma2(ull& d, ull a, ull b) {
    asm("fma.rn.f32x2 %0, %1, %2, %0;" : "+l"(d) : "l"(a), "l"(b));
}
__device__ __forceinline__ ull pack2(float lo, float hi) {
    ull r; asm("mov.b64 %0, {%1,%2};" : "=l"(r) : "f"(lo), "f"(hi)); return r;
}
__device__ __forceinline__ void unpack2(float& lo, float& hi, ull v) {
    asm("mov.b64 {%0,%1}, %2;" : "=f"(lo), "=f"(hi) : "l"(v));
}

// ---------------- device scratch ----------------
__device__ __align__(16) float g_wsrc[Hh * Dd];
__device__ __align__(16) float g_wdst[Hh * Dd];
__device__ __align__(16) float g_Wcat[Hh * Dd * Dd];     // [k][f], 1/H folded
__device__ __align__(16) float g_asrc[NBT * Hh];
__device__ __align__(16) float g_adst[NBT * Hh];
__device__ int g_rowptr[Nn + 1];
__device__ int g_esrc[ET];
__device__ __align__(16) float g_agg[(size_t)NBT * 256]; // ~64MB

// ---------------- K0: setup (block 0 = CSR, block 1 = weight prep) ----------------
// edge_index may be int32 or int64 (JAX x64-config). Probe: int64 => every odd
// 32-bit word in the first 5200 words is 0 (values < 325).
__global__ void k_setup(const int* __restrict__ ew,
                        const float* __restrict__ W,
                        const float* __restrict__ att_src,
                        const float* __restrict__ att_dst) {
    int tid = threadIdx.x;
    int bd = blockDim.x;      // 1024
    const unsigned full = 0xffffffffu;
    if (blockIdx.x == 1) {
        if (tid < 256) {
            int h = tid >> 6, d = tid & 63;
            float s1 = 0.f, s2 = 0.f;
            #pragma unroll 8
            for (int f = 0; f < 64; f++) {
                float w = W[(d * Hh + h) * 64 + f];
                s1 += w * att_src[h * 64 + f];
                s2 += w * att_dst[h * 64 + f];
            }
            g_wsrc[tid] = s1;
            g_wdst[tid] = s2;
        }
        for (int i = tid; i < Hh * Dd * Dd; i += bd) {
            int k = i >> 6, f = i & 63;
            int hh = k >> 6, dd = k & 63;
            g_Wcat[i] = W[(dd * Hh + hh) * 64 + f] * 0.25f;   // 1/H folded
        }
        return;
    }
    // ---- CSR build, deterministic (sorted by original edge id) ----
    __shared__ int sdst[ET];
    __shared__ int ssrc[ET];
    __shared__ int sslot[ET];
    __shared__ int scnt[Nn + 1];
    __shared__ int scur[Nn];
    __shared__ int s_is32;
    if (tid == 0) s_is32 = 0;
    __syncthreads();
    for (int i = tid; i < Ee; i += bd)
        if (ew[2 * i + 1] != 0) s_is32 = 1;
    __syncthreads();
    int is32 = s_is32;
    for (int i = tid; i < ET; i += bd) {
        if (i < Ee) {
            if (is32) { ssrc[i] = ew[i];         sdst[i] = ew[Ee + i]; }
            else      { ssrc[i] = ew[2 * i];     sdst[i] = ew[2 * (Ee + i)]; }
        } else {
            ssrc[i] = i - Ee;
            sdst[i] = i - Ee;
        }
    }
    for (int i = tid; i <= Nn; i += bd) scnt[i] = 0;
    __syncthreads();
    for (int i = tid; i < ET; i += bd) atomicAdd(&scnt[sdst[i] + 1], 1);
    __syncthreads();
    // warp-parallel inclusive prefix scan over scnt[0..Nn]
    if (tid < 32) {
        int carry = 0;
        for (int base = 0; base <= Nn; base += 32) {
            int i = base + tid;
            int v = (i <= Nn) ? scnt[i] : 0;
            #pragma unroll
            for (int o = 1; o < 32; o <<= 1) {
                int t = __shfl_up_sync(full, v, o);
                if (tid >= o) v += t;
            }
            v += carry;
            if (i <= Nn) scnt[i] = v;
            carry = __shfl_sync(full, v, 31);
        }
    }
    __syncthreads();
    for (int i = tid; i <= Nn; i += bd) g_rowptr[i] = scnt[i];
    for (int i = tid; i < Nn; i += bd) scur[i] = scnt[i];
    __syncthreads();
    for (int e = tid; e < ET; e += bd) {
        int pos = atomicAdd(&scur[sdst[e]], 1);
        sslot[pos] = e;
    }
    __syncthreads();
    for (int n = tid; n < Nn; n += bd) {
        int a = scnt[n], b = scnt[n + 1];
        for (int i = a + 1; i < b; i++) {      // sort by edge id -> deterministic
            int v = sslot[i];
            int j = i - 1;
            while (j >= a && sslot[j] > v) { sslot[j + 1] = sslot[j]; j--; }
            sslot[j + 1] = v;
        }
        for (int p = a; p < b; p++) g_esrc[p] = ssrc[sslot[p]];
    }
}

// ---------------- K1: attention logits, warp per (n,bt) ----------------
__global__ __launch_bounds__(256) void k_alpha(const float* __restrict__ x) {
    __shared__ float sw[512];
    int tid = threadIdx.x;
    sw[tid] = g_wsrc[tid];
    sw[256 + tid] = g_wdst[tid];
    __syncthreads();
    int gid = blockIdx.x * 8 + (tid >> 5);
    int lane = tid & 31;
    int n = gid / BT, bt = gid % BT;
    float2 xv = ((const float2*)(x + ((size_t)bt * Nn + n) * 64))[lane];
    float p[8];
    #pragma unroll
    for (int h = 0; h < 4; h++) {
        p[h]     = xv.x * sw[h * 64 + 2 * lane]       + xv.y * sw[h * 64 + 2 * lane + 1];
        p[4 + h] = xv.x * sw[256 + h * 64 + 2 * lane] + xv.y * sw[256 + h * 64 + 2 * lane + 1];
    }
    #pragma unroll
    for (int o = 16; o; o >>= 1) {
        #pragma unroll
        for (int j = 0; j < 8; j++) p[j] += __shfl_xor_sync(0xffffffffu, p[j], o);
    }
    int base = gid * 4;
    if (lane < 4) g_asrc[base + lane] = p[lane];
    else if (lane < 8) g_adst[base + lane - 4] = p[lane];
}

// ---------------- K2: segment softmax + aggregation ----------------
// No max-shift needed: |alpha| < ~2 for this problem's weight scales.
__device__ __forceinline__ float lrelu(float v) { return v >= 0.f ? v : 0.2f * v; }

__global__ __launch_bounds__(256) void k_agg(const float* __restrict__ x) {
    __shared__ int s_src[8][32];
    __shared__ __align__(16) ull s_cf[8][32][4];   // dup'd coef pairs {c,c}
    const unsigned full = 0xffffffffu;
    int tid = threadIdx.x;
    int w = tid >> 5, lane = tid & 31;
    int gid = blockIdx.x * 8 + w;
    int n = gid / BT, bt = gid % BT;
    int rs = g_rowptr[n], re = g_rowptr[n + 1];
    float4 adv = *(const float4*)(g_adst + gid * 4);

    float sm[4] = {0.f, 0.f, 0.f, 0.f};
    float c0[4] = {0.f, 0.f, 0.f, 0.f};
    int s0 = 0;
    int e0 = rs + lane;
    for (int e = e0; e < re; e += 32) {
        int s = g_esrc[e];
        float4 av = *(const float4*)(g_asrc + (s * BT + bt) * 4);
        float v0 = __expf(lrelu(av.x + adv.x));
        float v1 = __expf(lrelu(av.y + adv.y));
        float v2 = __expf(lrelu(av.z + adv.z));
        float v3 = __expf(lrelu(av.w + adv.w));
        sm[0] += v0; sm[1] += v1; sm[2] += v2; sm[3] += v3;
        if (e == e0) { s0 = s; c0[0] = v0; c0[1] = v1; c0[2] = v2; c0[3] = v3; }
    }
    #pragma unroll
    for (int o = 16; o; o >>= 1) {
        #pragma unroll
        for (int h = 0; h < 4; h++) sm[h] += __shfl_xor_sync(full, sm[h], o);
    }
    float inv[4];
    #pragma unroll
    for (int h = 0; h < 4; h++) inv[h] = 1.f / (sm[h] + 1e-16f);
    if (e0 < re) {
        s_src[w][lane] = s0;
        #pragma unroll
        for (int h = 0; h < 4; h++) {
            float c = c0[h] * inv[h];
            s_cf[w][lane][h] = pack2(c, c);
        }
    }
    __syncwarp();

    ull acc0 = 0, acc1 = 0, acc2 = 0, acc3 = 0;
    const float* xb = x + (size_t)bt * (Nn * 64);
    int deg = re - rs;
    int jmax = deg < 32 ? deg : 32;
    for (int j = 0; j < jmax; j++) {
        int src = s_src[w][j];
        ulonglong2 cA = *(const ulonglong2*)&s_cf[w][j][0];
        ulonglong2 cB = *(const ulonglong2*)&s_cf[w][j][2];
        ull xv = *(const ull*)(xb + src * 64 + 2 * lane);
        ffma2(acc0, xv, cA.x);
        ffma2(acc1, xv, cA.y);
        ffma2(acc2, xv, cB.x);
        ffma2(acc3, xv, cB.y);
    }
    for (int j = 32; j < deg; j++) {           // rare: degree > 32
        int src = g_esrc[rs + j];
        float4 av = *(const float4*)(g_asrc + (src * BT + bt) * 4);
        float cc0 = __expf(lrelu(av.x + adv.x)) * inv[0];
        float cc1 = __expf(lrelu(av.y + adv.y)) * inv[1];
        float cc2 = __expf(lrelu(av.z + adv.z)) * inv[2];
        float cc3 = __expf(lrelu(av.w + adv.w)) * inv[3];
        ull xv = *(const ull*)(xb + src * 64 + 2 * lane);
        ffma2(acc0, xv, pack2(cc0, cc0));
        ffma2(acc1, xv, pack2(cc1, cc1));
        ffma2(acc2, xv, pack2(cc2, cc2));
        ffma2(acc3, xv, pack2(cc3, cc3));
    }
    ull* ao = (ull*)(g_agg + (size_t)gid * 256 + 2 * lane);
    ao[0]  = acc0;     // h=0
    ao[32] = acc1;     // h=1
    ao[64] = acc2;
    ao[96] = acc3;
}

// ---------------- K3: GEMM [NBT,256]@[256,64] (FFMA2) + bias + residual + LN ----------------
// Small blocks (48 rows, 128 threads) -> ~8 blocks/SM so chunk-boundary
// convoys of independent blocks overlap.
#define GBM 48
#define ASTR 50
__global__ __launch_bounds__(128, 8) void k_gemm(const float* __restrict__ x,
                                                 const float* __restrict__ bias,
                                                 const float* __restrict__ gamma,
                                                 const float* __restrict__ beta,
                                                 float* __restrict__ out) {
    __shared__ __align__(16) float sm[5696];   // As[32][50]=1600 fl + Bs 2048 ull
    float* As = sm;
    ull* Bs = (ull*)(sm + 1600);               // [kk][c2][16 tcol][2]
    int tid = threadIdx.x;
    int tcol = tid & 15, trow = tid >> 4;      // trow 0..7
    int r0 = blockIdx.x * GBM;
    ull acc[3][4];
    #pragma unroll
    for (int i = 0; i < 3; i++)
        #pragma unroll
        for (int j = 0; j < 4; j++) acc[i][j] = 0ull;

    const float* Ab = g_agg + (size_t)r0 * 256;
    int arow = tid >> 3, q = tid & 7;          // arow 0..15
    int kB = tid >> 2;                         // 0..31 (kk for B fill)
    int f0 = (tid & 3) * 16;                   // 16 floats per thread
    for (int kc = 0; kc < 256; kc += 32) {
        __syncthreads();
        #pragma unroll
        for (int p = 0; p < 3; p++) {
            int row = p * 16 + arow;
            float4 v = *(const float4*)(Ab + (size_t)row * 256 + kc + q * 4);
            As[(q * 4 + 0) * ASTR + row] = v.x;
            As[(q * 4 + 1) * ASTR + row] = v.y;
            As[(q * 4 + 2) * ASTR + row] = v.z;
            As[(q * 4 + 3) * ASTR + row] = v.w;
        }
        {
            const float* wsrc = g_Wcat + (size_t)(kc + kB) * 64 + f0;
            #pragma unroll
            for (int p4 = 0; p4 < 4; p4++) {
                float4 v = *(const float4*)(wsrc + p4 * 4);
                float vv[4] = {v.x, v.y, v.z, v.w};
                #pragma unroll
                for (int j = 0; j < 4; j++) {
                    int f = f0 + p4 * 4 + j;
                    int c = f & 3, tc = f >> 2;
                    Bs[((kB * 2 + (c >> 1)) * 16 + tc) * 2 + (c & 1)] = pack2(vv[j], vv[j]);
                }
            }
        }
        __syncthreads();
        #pragma unroll
        for (int kk = 0; kk < 32; kk++) {
            ulonglong2 b01 = *(const ulonglong2*)&Bs[((kk * 2 + 0) * 16 + tcol) * 2];
            ulonglong2 b23 = *(const ulonglong2*)&Bs[((kk * 2 + 1) * 16 + tcol) * 2];
            const float* ak = As + kk * ASTR + 2 * trow;
            ull a0 = *(const ull*)(ak);
            ull a1 = *(const ull*)(ak + 16);
            ull a2 = *(const ull*)(ak + 32);
            ffma2(acc[0][0], a0, b01.x); ffma2(acc[0][1], a0, b01.y);
            ffma2(acc[0][2], a0, b23.x); ffma2(acc[0][3], a0, b23.y);
            ffma2(acc[1][0], a1, b01.x); ffma2(acc[1][1], a1, b01.y);
            ffma2(acc[1][2], a1, b23.x); ffma2(acc[1][3], a1, b23.y);
            ffma2(acc[2][0], a2, b01.x); ffma2(acc[2][1], a2, b01.y);
            ffma2(acc[2][2], a2, b23.x); ffma2(acc[2][3], a2, b23.y);
        }
    }
    __syncthreads();
    float* CS = sm;                            // 48x64 = 3072 floats
    #pragma unroll
    for (int i = 0; i < 3; i++) {
        int pr = trow + 8 * i;
        float l0, h0, l1, h1, l2, h2, l3, h3;
        unpack2(l0, h0, acc[i][0]);
        unpack2(l1, h1, acc[i][1]);
        unpack2(l2, h2, acc[i][2]);
        unpack2(l3, h3, acc[i][3]);
        *(float4*)&CS[(2 * pr) * 64 + tcol * 4]     = make_float4(l0, l1, l2, l3);
        *(float4*)&CS[(2 * pr + 1) * 64 + tcol * 4] = make_float4(h0, h1, h2, h3);
    }
    __syncthreads();

    // epilogue: warp per row, 12 rows per warp
    int lane = tid & 31, wid = tid >> 5;
    float2 bi = ((const float2*)bias)[lane];
    float2 ga = ((const float2*)gamma)[lane];
    float2 be = ((const float2*)beta)[lane];
    const unsigned full = 0xffffffffu;
    #pragma unroll
    for (int it = 0; it < 12; it++) {
        int row = wid * 12 + it;
        int r = r0 + row;
        int n = r / BT, bt = r % BT;
        size_t xo = ((size_t)bt * Nn + n) * 64;
        float2 c = *(const float2*)(CS + row * 64 + lane * 2);
        float2 xv = *(const float2*)(x + xo + lane * 2);
        float yx = xv.x + c.x + bi.x;
        float yy = xv.y + c.y + bi.y;
        float s = yx + yy;
        float s2 = yx * yx + yy * yy;
        #pragma unroll
        for (int o = 16; o; o >>= 1) {
            s += __shfl_xor_sync(full, s, o);
            s2 += __shfl_xor_sync(full, s2, o);
        }
        float mu = s * (1.f / 64.f);
        float var = s2 * (1.f / 64.f) - mu * mu;
        float rstd = rsqrtf(var + 1e-5f);
        float2 o2;
        o2.x = (yx - mu) * rstd * ga.x + be.x;
        o2.y = (yy - mu) * rstd * ga.y + be.y;
        *(float2*)(out + xo + lane * 2) = o2;
    }
}

// ---------------- launcher ----------------
extern "C" void kernel_launch(void* const* d_in, const int* in_sizes, int n_in,
                              void* d_out, int out_size) {
    const float* x        = (const float*)d_in[0];
    const float* W        = (const float*)d_in[1];
    const float* att_src  = (const float*)d_in[2];
    const float* att_dst  = (const float*)d_in[3];
    const float* bias     = (const float*)d_in[4];
    const float* gamma    = (const float*)d_in[5];
    const float* beta     = (const float*)d_in[6];
    const int*   edge     = (const int*)d_in[7];
    float* out = (float*)d_out;

    k_setup<<<2, 1024>>>(edge, W, att_src, att_dst);
    k_alpha<<<NBT / 8, 256>>>(x);
    k_agg<<<NBT / 8, 256>>>(x);
    k_gemm<<<NBT / GBM, 128>>>(x, bias, gamma, beta, out);
}

// round 10
// speedup vs baseline: 1.6354x; 1.6354x over previous
#include <cuda_runtime.h>
#include <cuda_bf16.h>
#include <mma.h>
#include <cstdint>

using namespace nvcuda;

#define Bn 16
#define Tn 12
#define BT 192          // B*T
#define Nn 325
#define Dd 64
#define Hh 4
#define Ee 2600
#define ET (Ee + Nn)    // 2925 edges incl. self loops
#define NBT (Nn * BT)   // 62400 (n,bt) pairs

typedef unsigned long long ull;

// ---------------- packed f32x2 helpers ----------------
__device__ __forceinline__ void ffma2(ull& d, ull a, ull b) {
    asm("fma.rn.f32x2 %0, %1, %2, %0;" : "+l"(d) : "l"(a), "l"(b));
}
__device__ __forceinline__ ull pack2(float lo, float hi) {
    ull r; asm("mov.b64 %0, {%1,%2};" : "=l"(r) : "f"(lo), "f"(hi)); return r;
}

// ---------------- device scratch ----------------
__device__ __align__(16) float g_wsrc[Hh * Dd];
__device__ __align__(16) float g_wdst[Hh * Dd];
__device__ __align__(16) float g_asrc[NBT * Hh];
__device__ __align__(16) float g_adst[NBT * Hh];
__device__ int g_rowptr[Nn + 1];
__device__ int g_esrc[ET];
__device__ __align__(16) float g_agg[(size_t)NBT * 256];          // ~64MB
__device__ __align__(16) __nv_bfloat16 g_Bh[256 * 64];            // B hi, [k][f], 1/H folded
__device__ __align__(16) __nv_bfloat16 g_Bl[256 * 64];            // B lo

// ---------------- K0: setup (block 0 = CSR, block 1 = weight prep) ----------------
// edge_index may be int32 or int64 (JAX x64-config). Probe: int64 => every odd
// 32-bit word in the first 5200 words is 0 (values < 325).
__global__ void k_setup(const int* __restrict__ ew,
                        const float* __restrict__ W,
                        const float* __restrict__ att_src,
                        const float* __restrict__ att_dst) {
    int tid = threadIdx.x;
    int bd = blockDim.x;      // 1024
    const unsigned full = 0xffffffffu;
    if (blockIdx.x == 1) {
        if (tid < 256) {
            int h = tid >> 6, d = tid & 63;
            float s1 = 0.f, s2 = 0.f;
            #pragma unroll 8
            for (int f = 0; f < 64; f++) {
                float w = W[(d * Hh + h) * 64 + f];
                s1 += w * att_src[h * 64 + f];
                s2 += w * att_dst[h * 64 + f];
            }
            g_wsrc[tid] = s1;
            g_wdst[tid] = s2;
        }
        for (int i = tid; i < 256 * 64; i += bd) {
            int k = i >> 6, f = i & 63;
            int h = k >> 6, d = k & 63;
            float w = W[(d * Hh + h) * 64 + f] * 0.25f;   // 1/H folded
            __nv_bfloat16 hi = __float2bfloat16(w);
            g_Bh[i] = hi;
            g_Bl[i] = __float2bfloat16(w - __bfloat162float(hi));
        }
        return;
    }
    // ---- CSR build, deterministic (sorted by original edge id) ----
    __shared__ int sdst[ET];
    __shared__ int ssrc[ET];
    __shared__ int sslot[ET];
    __shared__ int scnt[Nn + 1];
    __shared__ int scur[Nn];
    __shared__ int s_is32;
    if (tid == 0) s_is32 = 0;
    __syncthreads();
    for (int i = tid; i < Ee; i += bd)
        if (ew[2 * i + 1] != 0) s_is32 = 1;
    __syncthreads();
    int is32 = s_is32;
    for (int i = tid; i < ET; i += bd) {
        if (i < Ee) {
            if (is32) { ssrc[i] = ew[i];         sdst[i] = ew[Ee + i]; }
            else      { ssrc[i] = ew[2 * i];     sdst[i] = ew[2 * (Ee + i)]; }
        } else {
            ssrc[i] = i - Ee;
            sdst[i] = i - Ee;
        }
    }
    for (int i = tid; i <= Nn; i += bd) scnt[i] = 0;
    __syncthreads();
    for (int i = tid; i < ET; i += bd) atomicAdd(&scnt[sdst[i] + 1], 1);
    __syncthreads();
    if (tid < 32) {            // warp-parallel inclusive scan
        int carry = 0;
        for (int base = 0; base <= Nn; base += 32) {
            int i = base + tid;
            int v = (i <= Nn) ? scnt[i] : 0;
            #pragma unroll
            for (int o = 1; o < 32; o <<= 1) {
                int t = __shfl_up_sync(full, v, o);
                if (tid >= o) v += t;
            }
            v += carry;
            if (i <= Nn) scnt[i] = v;
            carry = __shfl_sync(full, v, 31);
        }
    }
    __syncthreads();
    for (int i = tid; i <= Nn; i += bd) g_rowptr[i] = scnt[i];
    for (int i = tid; i < Nn; i += bd) scur[i] = scnt[i];
    __syncthreads();
    for (int e = tid; e < ET; e += bd) {
        int pos = atomicAdd(&scur[sdst[e]], 1);
        sslot[pos] = e;
    }
    __syncthreads();
    for (int n = tid; n < Nn; n += bd) {
        int a = scnt[n], b = scnt[n + 1];
        for (int i = a + 1; i < b; i++) {      // sort by edge id -> deterministic
            int v = sslot[i];
            int j = i - 1;
            while (j >= a && sslot[j] > v) { sslot[j + 1] = sslot[j]; j--; }
            sslot[j + 1] = v;
        }
        for (int p = a; p < b; p++) g_esrc[p] = ssrc[sslot[p]];
    }
}

// ---------------- K1: attention logits, warp per (n,bt) ----------------
__global__ __launch_bounds__(256) void k_alpha(const float* __restrict__ x) {
    __shared__ float sw[512];
    int tid = threadIdx.x;
    sw[tid] = g_wsrc[tid];
    sw[256 + tid] = g_wdst[tid];
    __syncthreads();
    int gid = blockIdx.x * 8 + (tid >> 5);
    int lane = tid & 31;
    int n = gid / BT, bt = gid % BT;
    float2 xv = ((const float2*)(x + ((size_t)bt * Nn + n) * 64))[lane];
    float p[8];
    #pragma unroll
    for (int h = 0; h < 4; h++) {
        p[h]     = xv.x * sw[h * 64 + 2 * lane]       + xv.y * sw[h * 64 + 2 * lane + 1];
        p[4 + h] = xv.x * sw[256 + h * 64 + 2 * lane] + xv.y * sw[256 + h * 64 + 2 * lane + 1];
    }
    #pragma unroll
    for (int o = 16; o; o >>= 1) {
        #pragma unroll
        for (int j = 0; j < 8; j++) p[j] += __shfl_xor_sync(0xffffffffu, p[j], o);
    }
    int base = gid * 4;
    if (lane < 4) g_asrc[base + lane] = p[lane];
    else if (lane < 8) g_adst[base + lane - 4] = p[lane];
}

// ---------------- K2: segment softmax + aggregation ----------------
// No max-shift needed: |alpha| < ~2 for this problem's weight scales.
__device__ __forceinline__ float lrelu(float v) { return v >= 0.f ? v : 0.2f * v; }

__global__ __launch_bounds__(256) void k_agg(const float* __restrict__ x) {
    __shared__ int s_src[8][32];
    __shared__ __align__(16) ull s_cf[8][32][4];   // dup'd coef pairs {c,c}
    const unsigned full = 0xffffffffu;
    int tid = threadIdx.x;
    int w = tid >> 5, lane = tid & 31;
    int gid = blockIdx.x * 8 + w;
    int n = gid / BT, bt = gid % BT;
    int rs = g_rowptr[n], re = g_rowptr[n + 1];
    float4 adv = *(const float4*)(g_adst + gid * 4);

    float sm[4] = {0.f, 0.f, 0.f, 0.f};
    float c0[4] = {0.f, 0.f, 0.f, 0.f};
    int s0 = 0;
    int e0 = rs + lane;
    for (int e = e0; e < re; e += 32) {
        int s = g_esrc[e];
        float4 av = *(const float4*)(g_asrc + (s * BT + bt) * 4);
        float v0 = __expf(lrelu(av.x + adv.x));
        float v1 = __expf(lrelu(av.y + adv.y));
        float v2 = __expf(lrelu(av.z + adv.z));
        float v3 = __expf(lrelu(av.w + adv.w));
        sm[0] += v0; sm[1] += v1; sm[2] += v2; sm[3] += v3;
        if (e == e0) { s0 = s; c0[0] = v0; c0[1] = v1; c0[2] = v2; c0[3] = v3; }
    }
    #pragma unroll
    for (int o = 16; o; o >>= 1) {
        #pragma unroll
        for (int h = 0; h < 4; h++) sm[h] += __shfl_xor_sync(full, sm[h], o);
    }
    float inv[4];
    #pragma unroll
    for (int h = 0; h < 4; h++) inv[h] = 1.f / (sm[h] + 1e-16f);
    if (e0 < re) {
        s_src[w][lane] = s0;
        #pragma unroll
        for (int h = 0; h < 4; h++) {
            float c = c0[h] * inv[h];
            s_cf[w][lane][h] = pack2(c, c);
        }
    }
    __syncwarp();

    ull acc0 = 0, acc1 = 0, acc2 = 0, acc3 = 0;
    const float* xb = x + (size_t)bt * (Nn * 64);
    int deg = re - rs;
    int jmax = deg < 32 ? deg : 32;
    for (int j = 0; j < jmax; j++) {
        int src = s_src[w][j];
        ulonglong2 cA = *(const ulonglong2*)&s_cf[w][j][0];
        ulonglong2 cB = *(const ulonglong2*)&s_cf[w][j][2];
        ull xv = *(const ull*)(xb + src * 64 + 2 * lane);
        ffma2(acc0, xv, cA.x);
        ffma2(acc1, xv, cA.y);
        ffma2(acc2, xv, cB.x);
        ffma2(acc3, xv, cB.y);
    }
    for (int j = 32; j < deg; j++) {           // rare: degree > 32
        int src = g_esrc[rs + j];
        float4 av = *(const float4*)(g_asrc + (src * BT + bt) * 4);
        float cc0 = __expf(lrelu(av.x + adv.x)) * inv[0];
        float cc1 = __expf(lrelu(av.y + adv.y)) * inv[1];
        float cc2 = __expf(lrelu(av.z + adv.z)) * inv[2];
        float cc3 = __expf(lrelu(av.w + adv.w)) * inv[3];
        ull xv = *(const ull*)(xb + src * 64 + 2 * lane);
        ffma2(acc0, xv, pack2(cc0, cc0));
        ffma2(acc1, xv, pack2(cc1, cc1));
        ffma2(acc2, xv, pack2(cc2, cc2));
        ffma2(acc3, xv, pack2(cc3, cc3));
    }
    ull* ao = (ull*)(g_agg + (size_t)gid * 256 + 2 * lane);
    ao[0]  = acc0;     // h=0
    ao[32] = acc1;     // h=1
    ao[64] = acc2;
    ao[96] = acc3;
}

// ---------------- K3: WMMA bf16 hi/lo GEMM + bias + residual + LayerNorm ----------------
// Block: 96 rows x 64 cols, K=256 in 4 chunks of 64. 192 threads = 6 warps,
// warp = 16 rows. D = Ah*Bh + Ah*Bl + Al*Bh (f32 accum).
#define GBM 96
#define LDA 72           // padded bf16 leading dim
#define SZ_A (GBM * LDA)                 // 6912 bf16
#define SZ_B (64 * LDA)                  // 4608 bf16

__global__ __launch_bounds__(192) void k_gemm(const float* __restrict__ x,
                                              const float* __restrict__ bias,
                                              const float* __restrict__ gamma,
                                              const float* __restrict__ beta,
                                              float* __restrict__ out) {
    __shared__ __align__(16) __nv_bfloat16 smem[2 * SZ_A + 2 * SZ_B];  // 46080 B
    __nv_bfloat16* Ah = smem;
    __nv_bfloat16* Al = Ah + SZ_A;
    __nv_bfloat16* Bh = Al + SZ_A;
    __nv_bfloat16* Bl = Bh + SZ_B;
    float* CS = (float*)smem;            // alias for epilogue (96*64 f32 = 24576B)

    int tid = threadIdx.x;
    int w = tid / 32, lane = tid & 31;
    int r0 = blockIdx.x * GBM;
    const float* Ab = g_agg + (size_t)r0 * 256;

    wmma::fragment<wmma::accumulator, 16, 16, 16, float> acc[4];
    #pragma unroll
    for (int c = 0; c < 4; c++) wmma::fill_fragment(acc[c], 0.f);

    for (int kc = 0; kc < 256; kc += 64) {
        // ---- load A chunk: 96x64 f32 -> bf16 hi/lo ----
        #pragma unroll
        for (int i = 0; i < 8; i++) {
            int idx = tid + 192 * i;             // 0..1535
            int row = idx >> 4;
            int kq = (idx & 15) * 4;
            float4 v = *(const float4*)(Ab + (size_t)row * 256 + kc + kq);
            __nv_bfloat16 h0 = __float2bfloat16(v.x);
            __nv_bfloat16 h1 = __float2bfloat16(v.y);
            __nv_bfloat16 h2 = __float2bfloat16(v.z);
            __nv_bfloat16 h3 = __float2bfloat16(v.w);
            __nv_bfloat162* ph = (__nv_bfloat162*)(Ah + row * LDA + kq);
            __nv_bfloat162* pl = (__nv_bfloat162*)(Al + row * LDA + kq);
            ph[0] = __halves2bfloat162(h0, h1);
            ph[1] = __halves2bfloat162(h2, h3);
            pl[0] = __halves2bfloat162(__float2bfloat16(v.x - __bfloat162float(h0)),
                                       __float2bfloat16(v.y - __bfloat162float(h1)));
            pl[1] = __halves2bfloat162(__float2bfloat16(v.z - __bfloat162float(h2)),
                                       __float2bfloat16(v.w - __bfloat162float(h3)));
        }
        // ---- load B chunk: 64x64 bf16 hi/lo (pre-split) ----
        #pragma unroll
        for (int i = 0; i < 3; i++) {
            int idx = tid + 192 * i;             // need 0..511
            if (idx < 512) {
                int row = idx >> 3;
                int f0 = (idx & 7) * 8;
                *(uint4*)(Bh + row * LDA + f0) =
                    *(const uint4*)(g_Bh + (size_t)(kc + row) * 64 + f0);
                *(uint4*)(Bl + row * LDA + f0) =
                    *(const uint4*)(g_Bl + (size_t)(kc + row) * 64 + f0);
            }
        }
        __syncthreads();

        // ---- 4 k-steps of m16n16k16 ----
        #pragma unroll
        for (int ks = 0; ks < 4; ks++) {
            wmma::fragment<wmma::matrix_a, 16, 16, 16, __nv_bfloat16, wmma::row_major> fah, fal;
            wmma::load_matrix_sync(fah, Ah + (w * 16) * LDA + ks * 16, LDA);
            wmma::load_matrix_sync(fal, Al + (w * 16) * LDA + ks * 16, LDA);
            #pragma unroll
            for (int c = 0; c < 4; c++) {
                wmma::fragment<wmma::matrix_b, 16, 16, 16, __nv_bfloat16, wmma::row_major> fbh, fbl;
                wmma::load_matrix_sync(fbh, Bh + (ks * 16) * LDA + c * 16, LDA);
                wmma::load_matrix_sync(fbl, Bl + (ks * 16) * LDA + c * 16, LDA);
                wmma::mma_sync(acc[c], fah, fbh, acc[c]);
                wmma::mma_sync(acc[c], fah, fbl, acc[c]);
                wmma::mma_sync(acc[c], fal, fbh, acc[c]);
            }
        }
        __syncthreads();
    }

    // ---- stage C into shared ----
    #pragma unroll
    for (int c = 0; c < 4; c++)
        wmma::store_matrix_sync(CS + (w * 16) * 64 + c * 16, acc[c], 64, wmma::mem_row_major);
    __syncthreads();

    // ---- epilogue: bias + residual + LayerNorm, warp per row, 16 rows/warp ----
    float2 bi = ((const float2*)bias)[lane];
    float2 ga = ((const float2*)gamma)[lane];
    float2 be = ((const float2*)beta)[lane];
    const unsigned full = 0xffffffffu;
    #pragma unroll
    for (int it = 0; it < 16; it++) {
        int row = w * 16 + it;
        int r = r0 + row;
        int n = r / BT, bt = r % BT;
        size_t xo = ((size_t)bt * Nn + n) * 64;
        float2 cc = *(const float2*)(CS + row * 64 + lane * 2);
        float2 xv = *(const float2*)(x + xo + lane * 2);
        float yx = xv.x + cc.x + bi.x;
        float yy = xv.y + cc.y + bi.y;
        float s = yx + yy;
        float s2 = yx * yx + yy * yy;
        #pragma unroll
        for (int o = 16; o; o >>= 1) {
            s += __shfl_xor_sync(full, s, o);
            s2 += __shfl_xor_sync(full, s2, o);
        }
        float mu = s * (1.f / 64.f);
        float var = s2 * (1.f / 64.f) - mu * mu;
        float rstd = rsqrtf(var + 1e-5f);
        float2 o2;
        o2.x = (yx - mu) * rstd * ga.x + be.x;
        o2.y = (yy - mu) * rstd * ga.y + be.y;
        *(float2*)(out + xo + lane * 2) = o2;
    }
}

// ---------------- launcher ----------------
extern "C" void kernel_launch(void* const* d_in, const int* in_sizes, int n_in,
                              void* d_out, int out_size) {
    const float* x        = (const float*)d_in[0];
    const float* W        = (const float*)d_in[1];
    const float* att_src  = (const float*)d_in[2];
    const float* att_dst  = (const float*)d_in[3];
    const float* bias     = (const float*)d_in[4];
    const float* gamma    = (const float*)d_in[5];
    const float* beta     = (const float*)d_in[6];
    const int*   edge     = (const int*)d_in[7];
    float* out = (float*)d_out;

    k_setup<<<2, 1024>>>(edge, W, att_src, att_dst);
    k_alpha<<<NBT / 8, 256>>>(x);
    k_agg<<<NBT / 8, 256>>>(x);
    k_gemm<<<NBT / GBM, 192>>>(x, bias, gamma, beta, out);
}